// round 1
// baseline (speedup 1.0000x reference)
#include <cuda_runtime.h>

// ---------------- problem constants ----------------
constexpr int B    = 8;
constexpr int C    = 5;
constexpr int NN   = 512;   // nodes
constexpr int FIN  = 768;
constexpr int H    = 4;
constexpr int DHID = 128;
constexpr int DOUT = 64;
constexpr int HD   = H * DHID;   // 512
constexpr int HD2  = H * DOUT;   // 256
constexpr int BC   = B * C;      // 40

// ---------------- scratch (device globals; no allocation allowed) ----------------
__device__ __align__(256) float g_feat[(size_t)BC * NN * HD];   // 41.9 MB
__device__ __align__(256) float g_h   [(size_t)BC * NN * HD];   // 41.9 MB
__device__ __align__(256) float g_out2[(size_t)BC * NN * HD2];  // 21.0 MB
__device__ __align__(256) float g_el  [BC * H * NN];
__device__ __align__(256) float g_er  [BC * H * NN];
__device__ __align__(256) float g_m   [BC * H * NN];
__device__ __align__(256) float g_s   [BC * H * NN];

// ---------------- GEMM: C[bc] (512 x Nn) = A[bc] (512 x K) @ W[c] (K x Nn) ----------------
// 64x64 tile, BK=16, 4x4 per thread, 256 threads.
__global__ void gemm64(const float* __restrict__ A, const float* __restrict__ W,
                       float* __restrict__ Co, int K, int Nn,
                       size_t aSB, size_t aSC) {
    __shared__ float As[16][64];
    __shared__ float Bs[16][64];

    int bc = blockIdx.z;
    int b  = bc / C, c = bc % C;
    const float* Ab = A + (size_t)b * aSB + (size_t)c * aSC;
    const float* Wc = W + (size_t)c * K * Nn;
    float*       Cb = Co + (size_t)bc * NN * Nn;

    int m0 = blockIdx.y * 64, n0 = blockIdx.x * 64;
    int tid = threadIdx.x;
    int tx = tid % 16, ty = tid / 16;

    int arow  = tid >> 2;          // 0..63
    int acolk = (tid & 3) * 4;     // 0..12
    int brow  = tid >> 4;          // 0..15
    int bcol  = (tid & 15) * 4;    // 0..60

    float acc[4][4] = {};

    for (int k0 = 0; k0 < K; k0 += 16) {
        float4 av = *(const float4*)(Ab + (size_t)(m0 + arow) * K + k0 + acolk);
        float4 bv = *(const float4*)(Wc + (size_t)(k0 + brow) * Nn + n0 + bcol);
        As[acolk + 0][arow] = av.x;
        As[acolk + 1][arow] = av.y;
        As[acolk + 2][arow] = av.z;
        As[acolk + 3][arow] = av.w;
        *(float4*)&Bs[brow][bcol] = bv;
        __syncthreads();
#pragma unroll
        for (int k = 0; k < 16; k++) {
            float4 a4 = *(const float4*)&As[k][ty * 4];
            float4 b4 = *(const float4*)&Bs[k][tx * 4];
            float aa[4] = {a4.x, a4.y, a4.z, a4.w};
            float bb[4] = {b4.x, b4.y, b4.z, b4.w};
#pragma unroll
            for (int i = 0; i < 4; i++)
#pragma unroll
                for (int j = 0; j < 4; j++) acc[i][j] = fmaf(aa[i], bb[j], acc[i][j]);
        }
        __syncthreads();
    }
#pragma unroll
    for (int i = 0; i < 4; i++) {
        float4 v = make_float4(acc[i][0], acc[i][1], acc[i][2], acc[i][3]);
        *(float4*)(Cb + (size_t)(m0 + ty * 4 + i) * Nn + n0 + tx * 4) = v;
    }
}

// ---------------- el/er: per-head dot products of feat rows with a_l / a_r ----------------
// grid = BC*NN blocks, 128 threads (warp per head)
__global__ void elr_kernel(const float* __restrict__ feat,
                           const float* __restrict__ al,
                           const float* __restrict__ ar,
                           float* __restrict__ el, float* __restrict__ er, int D) {
    int bcn = blockIdx.x;            // bc*NN + i
    int bc = bcn / NN, i = bcn % NN;
    int c = bc % C;
    int h = threadIdx.x >> 5, lane = threadIdx.x & 31;

    const float* f   = feat + (size_t)bcn * (H * D) + h * D;
    const float* alh = al + (size_t)(c * H + h) * D;
    const float* arh = ar + (size_t)(c * H + h) * D;

    float sl = 0.f, sr = 0.f;
    for (int d = lane; d < D; d += 32) {
        float v = f[d];
        sl = fmaf(v, alh[d], sl);
        sr = fmaf(v, arh[d], sr);
    }
#pragma unroll
    for (int o = 16; o; o >>= 1) {
        sl += __shfl_down_sync(0xffffffffu, sl, o);
        sr += __shfl_down_sync(0xffffffffu, sr, o);
    }
    if (lane == 0) {
        el[((size_t)bc * H + h) * NN + i] = sl;
        er[((size_t)bc * H + h) * NN + i] = sr;
    }
}

// ---------------- softmax stats over source axis i (masked): m[j,h], s[j,h] ----------------
// grid = (NN/64, BC), 256 threads: (ti=tid/64 in 0..3) x (j=tid%64)
__global__ void stats_kernel(const float* __restrict__ adj,
                             const float* __restrict__ el,
                             const float* __restrict__ er,
                             float* __restrict__ gm, float* __restrict__ gs) {
    __shared__ float el_s[H][NN];
    __shared__ float er_s[H][64];
    __shared__ float red[4][H][64];

    int bc = blockIdx.y;
    int j0 = blockIdx.x * 64;
    const float* adj_bc = adj + (size_t)bc * NN * NN;
    int tid = threadIdx.x;

    for (int t = tid; t < H * NN; t += 256) el_s[t / NN][t % NN] = el[(size_t)bc * H * NN + t];
    for (int t = tid; t < H * 64; t += 256)
        er_s[t >> 6][t & 63] = er[((size_t)bc * H + (t >> 6)) * NN + j0 + (t & 63)];
    __syncthreads();

    int j = tid & 63, ti = tid >> 6;
    float mx[H];
#pragma unroll
    for (int h = 0; h < H; h++) mx[h] = -3.402823466e38f;

    for (int i = ti; i < NN; i += 4) {
        float a = adj_bc[(size_t)i * NN + j0 + j];
        if (a > 0.f) {
#pragma unroll
            for (int h = 0; h < H; h++) {
                float e = el_s[h][i] + er_s[h][j];
                e = e > 0.f ? e : 0.2f * e;
                mx[h] = fmaxf(mx[h], e);
            }
        }
    }
#pragma unroll
    for (int h = 0; h < H; h++) red[ti][h][j] = mx[h];
    __syncthreads();
#pragma unroll
    for (int h = 0; h < H; h++)
        mx[h] = fmaxf(fmaxf(red[0][h][j], red[1][h][j]), fmaxf(red[2][h][j], red[3][h][j]));
    __syncthreads();

    float sm[H] = {0.f, 0.f, 0.f, 0.f};
    for (int i = ti; i < NN; i += 4) {
        float a = adj_bc[(size_t)i * NN + j0 + j];
        if (a > 0.f) {
#pragma unroll
            for (int h = 0; h < H; h++) {
                float e = el_s[h][i] + er_s[h][j];
                e = e > 0.f ? e : 0.2f * e;
                sm[h] += __expf(e - mx[h]);
            }
        }
    }
#pragma unroll
    for (int h = 0; h < H; h++) red[ti][h][j] = sm[h];
    __syncthreads();
    if (ti == 0) {
#pragma unroll
        for (int h = 0; h < H; h++) {
            float s = red[0][h][j] + red[1][h][j] + red[2][h][j] + red[3][h][j];
            gm[((size_t)bc * H + h) * NN + j0 + j] = mx[h];
            gs[((size_t)bc * H + h) * NN + j0 + j] = s;
        }
    }
}

// ---------------- aggregation: out[j,h,d] = (1/max(s,1e-9)) * sum_i p[i,j,h]*feat[i,h,d] ----
// block: 64 j x D d tile for one (bc, h); loops i in blocks of 16, recomputing p.
template <int D, bool RELU>
__global__ void agg_kernel(const float* __restrict__ adj,
                           const float* __restrict__ feat,
                           const float* __restrict__ el,
                           const float* __restrict__ er,
                           const float* __restrict__ gm,
                           const float* __restrict__ gs,
                           const float* __restrict__ bias,
                           float* __restrict__ out) {
    constexpr int TN = D / 16;   // 8 (D=128) or 4 (D=64)
    __shared__ float p_s[16][64];
    __shared__ float f_s[16][D];
    __shared__ float el_s[NN];
    __shared__ float er_s[64], m_s[64], sc_s[64];

    int bc = blockIdx.z, h = blockIdx.y;
    int c = bc % C;
    int j0 = blockIdx.x * 64;
    int tid = threadIdx.x;

    const float* adj_bc = adj + (size_t)bc * NN * NN;
    const float* elh = el + (size_t)(bc * H + h) * NN;

    el_s[tid]       = elh[tid];
    el_s[tid + 256] = elh[tid + 256];
    if (tid < 64) {
        er_s[tid] = er[(size_t)(bc * H + h) * NN + j0 + tid];
        m_s[tid]  = gm[(size_t)(bc * H + h) * NN + j0 + tid];
        float sv  = gs[(size_t)(bc * H + h) * NN + j0 + tid];
        sc_s[tid] = 1.0f / fmaxf(sv, 1e-9f);
    }
    __syncthreads();

    int tx = tid % 16, ty = tid / 16;
    int jj0 = ty * 4, dd0 = tx * TN;
    int pi = tid >> 6, pj = tid & 63;

    float acc[4][TN] = {};

    for (int ib = 0; ib < NN; ib += 16) {
        // load feat tile (16 x D)
#pragma unroll
        for (int l = 0; l < D / 64; l++) {
            int slot = tid + l * 256;
            int r = slot / (D / 4), c4 = slot % (D / 4);
            float4 v = *(const float4*)(feat + ((size_t)bc * NN + ib + r) * (H * D) + h * D + c4 * 4);
            *(float4*)&f_s[r][c4 * 4] = v;
        }
        // compute p tile (16 x 64)
#pragma unroll
        for (int rr = 0; rr < 4; rr++) {
            int i = pi + rr * 4;
            float a = adj_bc[(size_t)(ib + i) * NN + j0 + pj];
            float p = 0.f;
            if (a > 0.f) {
                float e = el_s[ib + i] + er_s[pj];
                e = e > 0.f ? e : 0.2f * e;
                p = __expf(e - m_s[pj]);
            }
            p_s[i][pj] = p;
        }
        __syncthreads();
#pragma unroll
        for (int i = 0; i < 16; i++) {
            float pv[4];
            *(float4*)pv = *(const float4*)&p_s[i][jj0];
            float fv[TN];
#pragma unroll
            for (int q = 0; q < TN / 4; q++)
                *(float4*)&fv[q * 4] = *(const float4*)&f_s[i][dd0 + q * 4];
#pragma unroll
            for (int jj = 0; jj < 4; jj++)
#pragma unroll
                for (int dd = 0; dd < TN; dd++) acc[jj][dd] = fmaf(pv[jj], fv[dd], acc[jj][dd]);
        }
        __syncthreads();
    }

    const float* bh = bias + (size_t)c * (H * D) + h * D;
#pragma unroll
    for (int jj = 0; jj < 4; jj++) {
        int j = j0 + jj0 + jj;
        float sc = sc_s[jj0 + jj];
        float vals[TN];
#pragma unroll
        for (int dd = 0; dd < TN; dd++) {
            float v = acc[jj][dd] * sc + bh[dd0 + dd];
            if (RELU) v = fmaxf(v, 0.f);
            vals[dd] = v;
        }
#pragma unroll
        for (int q = 0; q < TN / 4; q++)
            *(float4*)(out + ((size_t)bc * NN + j) * (H * D) + h * D + dd0 + q * 4) =
                *(float4*)&vals[q * 4];
    }
}

// ---------------- head-mean + channel concat: out[b,n,c*64+d] ----------------
__global__ void mean_kernel(const float* __restrict__ in2, float* __restrict__ out) {
    int idx = blockIdx.x * 256 + threadIdx.x;
    if (idx >= B * NN * C * DOUT) return;
    int d = idx % DOUT;
    int c = (idx / DOUT) % C;
    int n = (idx / (DOUT * C)) % NN;
    int b = idx / (DOUT * C * NN);
    const float* p = in2 + ((size_t)(b * C + c) * NN + n) * HD2 + d;
    out[idx] = 0.25f * (p[0] + p[DOUT] + p[2 * DOUT] + p[3 * DOUT]);
}

// ---------------- launch ----------------
extern "C" void kernel_launch(void* const* d_in, const int* in_sizes, int n_in,
                              void* d_out, int out_size) {
    const float* x   = (const float*)d_in[0];
    const float* adj = (const float*)d_in[1];
    const float* W0  = (const float*)d_in[2];
    const float* al0 = (const float*)d_in[3];
    const float* ar0 = (const float*)d_in[4];
    const float* b0  = (const float*)d_in[5];
    const float* W1  = (const float*)d_in[6];
    const float* al1 = (const float*)d_in[7];
    const float* ar1 = (const float*)d_in[8];
    const float* b1  = (const float*)d_in[9];
    const float* W2  = (const float*)d_in[10];
    const float* al2 = (const float*)d_in[11];
    const float* ar2 = (const float*)d_in[12];
    const float* b2  = (const float*)d_in[13];
    float* out = (float*)d_out;

    float *feat, *hbuf, *el, *er, *gm, *gs, *out2;
    cudaGetSymbolAddress((void**)&feat, g_feat);
    cudaGetSymbolAddress((void**)&hbuf, g_h);
    cudaGetSymbolAddress((void**)&el,   g_el);
    cudaGetSymbolAddress((void**)&er,   g_er);
    cudaGetSymbolAddress((void**)&gm,   g_m);
    cudaGetSymbolAddress((void**)&gs,   g_s);
    cudaGetSymbolAddress((void**)&out2, g_out2);

    dim3 t256(256);

    // ---- layer 0 (input: x[:,0], shared across channels) ----
    gemm64<<<dim3(HD / 64, NN / 64, BC), t256>>>(x, W0, feat, FIN, HD,
                                                 (size_t)C * NN * FIN, 0);
    elr_kernel<<<BC * NN, 128>>>(feat, al0, ar0, el, er, DHID);
    stats_kernel<<<dim3(NN / 64, BC), t256>>>(adj, el, er, gm, gs);
    agg_kernel<DHID, true><<<dim3(NN / 64, H, BC), t256>>>(adj, feat, el, er, gm, gs, b0, hbuf);

    // ---- layer 1 ----
    gemm64<<<dim3(HD / 64, NN / 64, BC), t256>>>(hbuf, W1, feat, HD, HD,
                                                 (size_t)C * NN * HD, (size_t)NN * HD);
    elr_kernel<<<BC * NN, 128>>>(feat, al1, ar1, el, er, DHID);
    stats_kernel<<<dim3(NN / 64, BC), t256>>>(adj, el, er, gm, gs);
    agg_kernel<DHID, true><<<dim3(NN / 64, H, BC), t256>>>(adj, feat, el, er, gm, gs, b1, hbuf);

    // ---- layer 2 ----
    gemm64<<<dim3(HD2 / 64, NN / 64, BC), t256>>>(hbuf, W2, feat, HD, HD2,
                                                  (size_t)C * NN * HD, (size_t)NN * HD);
    elr_kernel<<<BC * NN, 128>>>(feat, al2, ar2, el, er, DOUT);
    stats_kernel<<<dim3(NN / 64, BC), t256>>>(adj, el, er, gm, gs);
    agg_kernel<DOUT, false><<<dim3(NN / 64, H, BC), t256>>>(adj, feat, el, er, gm, gs, b2, out2);

    // ---- head mean + concat ----
    mean_kernel<<<(B * NN * C * DOUT + 255) / 256, t256>>>(out2, out);
}

// round 2
// speedup vs baseline: 1.1129x; 1.1129x over previous
#include <cuda_runtime.h>

// ---------------- problem constants ----------------
constexpr int B    = 8;
constexpr int C    = 5;
constexpr int NN   = 512;   // nodes
constexpr int FIN  = 768;
constexpr int H    = 4;
constexpr int DHID = 128;
constexpr int DOUT = 64;
constexpr int HD   = H * DHID;   // 512
constexpr int HD2  = H * DOUT;   // 256
constexpr int BC   = B * C;      // 40

// ---------------- scratch (device globals; no allocation allowed) ----------------
__device__ __align__(256) float g_feat[(size_t)BC * NN * HD];   // 41.9 MB
__device__ __align__(256) float g_h   [(size_t)BC * NN * HD];   // 41.9 MB
__device__ __align__(256) float g_out2[(size_t)BC * NN * HD2];  // 21.0 MB
__device__ __align__(256) float g_el  [BC * H * NN];
__device__ __align__(256) float g_er  [BC * H * NN];

// ---------------- GEMM: C[bc] (512 x Nn) = A[bc] (512 x K) @ W[c] (K x Nn) ----------------
// 128x128 tile, BK=16, 8x8 per thread, 256 threads.
__global__ void gemm128(const float* __restrict__ A, const float* __restrict__ W,
                        float* __restrict__ Co, int K, int Nn,
                        size_t aSB, size_t aSC) {
    __shared__ float As[16][128];
    __shared__ float Bs[16][128];

    int bc = blockIdx.z;
    int b  = bc / C, c = bc % C;
    const float* Ab = A + (size_t)b * aSB + (size_t)c * aSC;
    const float* Wc = W + (size_t)c * K * Nn;
    float*       Cb = Co + (size_t)bc * NN * Nn;

    int m0 = blockIdx.y * 128, n0 = blockIdx.x * 128;
    int tid = threadIdx.x;
    int tx = tid % 16, ty = tid / 16;

    float acc[8][8] = {};

    for (int k0 = 0; k0 < K; k0 += 16) {
        // A: 128 rows x 16 k  (512 float4 slots: row = s>>2, kq = s&3), transpose into As[k][m]
#pragma unroll
        for (int l = 0; l < 2; l++) {
            int s = tid + l * 256;
            int row = s >> 2, kq = s & 3;
            float4 av = *(const float4*)(Ab + (size_t)(m0 + row) * K + k0 + kq * 4);
            As[kq * 4 + 0][row] = av.x;
            As[kq * 4 + 1][row] = av.y;
            As[kq * 4 + 2][row] = av.z;
            As[kq * 4 + 3][row] = av.w;
        }
        // B: 16 k-rows x 128 n  (512 float4 slots: krow = s>>5, nq = s&31)
#pragma unroll
        for (int l = 0; l < 2; l++) {
            int s = tid + l * 256;
            int krow = s >> 5, nq = s & 31;
            float4 bv = *(const float4*)(Wc + (size_t)(k0 + krow) * Nn + n0 + nq * 4);
            *(float4*)&Bs[krow][nq * 4] = bv;
        }
        __syncthreads();
#pragma unroll
        for (int k = 0; k < 16; k++) {
            float a[8], bb[8];
            *(float4*)&a[0]  = *(const float4*)&As[k][ty * 8];
            *(float4*)&a[4]  = *(const float4*)&As[k][ty * 8 + 4];
            *(float4*)&bb[0] = *(const float4*)&Bs[k][tx * 8];
            *(float4*)&bb[4] = *(const float4*)&Bs[k][tx * 8 + 4];
#pragma unroll
            for (int i = 0; i < 8; i++)
#pragma unroll
                for (int j = 0; j < 8; j++) acc[i][j] = fmaf(a[i], bb[j], acc[i][j]);
        }
        __syncthreads();
    }
#pragma unroll
    for (int i = 0; i < 8; i++) {
        float* dst = Cb + (size_t)(m0 + ty * 8 + i) * Nn + n0 + tx * 8;
        *(float4*)dst       = *(float4*)&acc[i][0];
        *(float4*)(dst + 4) = *(float4*)&acc[i][4];
    }
}

// ---------------- el/er: per-head dot products of feat rows with a_l / a_r ----------------
__global__ void elr_kernel(const float* __restrict__ feat,
                           const float* __restrict__ al,
                           const float* __restrict__ ar,
                           float* __restrict__ el, float* __restrict__ er, int D) {
    int bcn = blockIdx.x;            // bc*NN + i
    int bc = bcn / NN, i = bcn % NN;
    int c = bc % C;
    int h = threadIdx.x >> 5, lane = threadIdx.x & 31;

    const float* f   = feat + (size_t)bcn * (H * D) + h * D;
    const float* alh = al + (size_t)(c * H + h) * D;
    const float* arh = ar + (size_t)(c * H + h) * D;

    float sl = 0.f, sr = 0.f;
    for (int d = lane; d < D; d += 32) {
        float v = f[d];
        sl = fmaf(v, alh[d], sl);
        sr = fmaf(v, arh[d], sr);
    }
#pragma unroll
    for (int o = 16; o; o >>= 1) {
        sl += __shfl_down_sync(0xffffffffu, sl, o);
        sr += __shfl_down_sync(0xffffffffu, sr, o);
    }
    if (lane == 0) {
        el[((size_t)bc * H + h) * NN + i] = sl;
        er[((size_t)bc * H + h) * NN + i] = sr;
    }
}

// ---------------- fused softmax + aggregation ----------------
// Softmax shift m_j = leaky(max_i el_i + er_j) uses the UNMASKED max of el:
// leaky_relu is monotone, so this upper-bounds the true masked max, and
// alpha = p/s is exactly invariant to the shift (s stays >> 1e-9 guard).
// Each block: one (bc, h), 128 j-columns, full D. 256 threads, 8x(D/16) regs.
// s = sum_i p is accumulated on the fly (each thread owns one j).
template <int D, bool RELU>
__global__ void agg_kernel(const float* __restrict__ adj,
                           const float* __restrict__ feat,
                           const float* __restrict__ el,
                           const float* __restrict__ er,
                           const float* __restrict__ bias,
                           float* __restrict__ out) {
    constexpr int TN = D / 16;            // 8 (D=128) or 4 (D=64)
    __shared__ float el_s[NN];
    __shared__ float er_s[128], m_s[128], sc_s[128];
    __shared__ float p_s[16][128];
    __shared__ float f_s[16][D];
    __shared__ float red[8];
    __shared__ float s_red[2][128];

    int bc = blockIdx.z, h = blockIdx.y;
    int c = bc % C;
    int j0 = blockIdx.x * 128;
    int tid = threadIdx.x;
    int lane = tid & 31, warp = tid >> 5;

    const float* adj_bc = adj + (size_t)bc * NN * NN;
    const float* elh = el + (size_t)(bc * H + h) * NN;
    const float* erh = er + (size_t)(bc * H + h) * NN;

    float e0 = elh[tid], e1 = elh[tid + 256];
    el_s[tid] = e0; el_s[tid + 256] = e1;
    if (tid < 128) er_s[tid] = erh[j0 + tid];

    // unmasked max of el (block reduce)
    float v = fmaxf(e0, e1);
#pragma unroll
    for (int o = 16; o; o >>= 1) v = fmaxf(v, __shfl_xor_sync(0xffffffffu, v, o));
    if (lane == 0) red[warp] = v;
    __syncthreads();
    if (tid == 0) {
        float m = red[0];
#pragma unroll
        for (int w = 1; w < 8; w++) m = fmaxf(m, red[w]);
        red[0] = m;
    }
    __syncthreads();
    if (tid < 128) {
        float e = red[0] + er_s[tid];
        m_s[tid] = e > 0.f ? e : 0.2f * e;
    }
    __syncthreads();

    int tx = tid % 16, ty = tid / 16;
    int jj0 = ty * 8, dd0 = tx * TN;
    int pj = tid & 127, pi0 = tid >> 7;   // p-tile: col pj, rows pi0, pi0+2, ...

    float acc[8][TN] = {};
    float s_priv = 0.f;

    for (int ib = 0; ib < NN; ib += 16) {
        // load feat tile (16 x D)
#pragma unroll
        for (int l = 0; l < (16 * D / 4) / 256; l++) {
            int s = tid + l * 256;
            int r = s / (D / 4), cq = s % (D / 4);
            float4 fv4 = *(const float4*)(feat + ((size_t)bc * NN + ib + r) * (H * D) + h * D + cq * 4);
            *(float4*)&f_s[r][cq * 4] = fv4;
        }
        // compute p tile (16 x 128); accumulate s for the owned column
#pragma unroll
        for (int q = 0; q < 8; q++) {
            int i = pi0 + q * 2;
            float a = adj_bc[(size_t)(ib + i) * NN + j0 + pj];
            float p = 0.f;
            if (a > 0.f) {
                float e = el_s[ib + i] + er_s[pj];
                e = e > 0.f ? e : 0.2f * e;
                p = __expf(e - m_s[pj]);
                s_priv += p;
            }
            p_s[i][pj] = p;
        }
        __syncthreads();
#pragma unroll
        for (int i = 0; i < 16; i++) {
            float pv[8], fv[TN];
            *(float4*)&pv[0] = *(const float4*)&p_s[i][jj0];
            *(float4*)&pv[4] = *(const float4*)&p_s[i][jj0 + 4];
#pragma unroll
            for (int q = 0; q < TN / 4; q++)
                *(float4*)&fv[q * 4] = *(const float4*)&f_s[i][dd0 + q * 4];
#pragma unroll
            for (int jj = 0; jj < 8; jj++)
#pragma unroll
                for (int dd = 0; dd < TN; dd++) acc[jj][dd] = fmaf(pv[jj], fv[dd], acc[jj][dd]);
        }
        __syncthreads();
    }

    // combine s across the two i-layers, form 1/max(s,1e-9)
    s_red[pi0][pj] = s_priv;
    __syncthreads();
    if (tid < 128) sc_s[tid] = 1.0f / fmaxf(s_red[0][tid] + s_red[1][tid], 1e-9f);
    __syncthreads();

    const float* bh = bias + (size_t)c * (H * D) + h * D;
#pragma unroll
    for (int jj = 0; jj < 8; jj++) {
        int j = j0 + jj0 + jj;
        float sc = sc_s[jj0 + jj];
        float vals[TN];
#pragma unroll
        for (int dd = 0; dd < TN; dd++) {
            float o = acc[jj][dd] * sc + bh[dd0 + dd];
            if (RELU) o = fmaxf(o, 0.f);
            vals[dd] = o;
        }
#pragma unroll
        for (int q = 0; q < TN / 4; q++)
            *(float4*)(out + ((size_t)bc * NN + j) * (H * D) + h * D + dd0 + q * 4) =
                *(float4*)&vals[q * 4];
    }
}

// ---------------- head-mean + channel concat: out[b,n,c*64+d] ----------------
__global__ void mean_kernel(const float* __restrict__ in2, float* __restrict__ out) {
    int idx = blockIdx.x * 256 + threadIdx.x;
    if (idx >= B * NN * C * DOUT) return;
    int d = idx % DOUT;
    int c = (idx / DOUT) % C;
    int n = (idx / (DOUT * C)) % NN;
    int b = idx / (DOUT * C * NN);
    const float* p = in2 + ((size_t)(b * C + c) * NN + n) * HD2 + d;
    out[idx] = 0.25f * (p[0] + p[DOUT] + p[2 * DOUT] + p[3 * DOUT]);
}

// ---------------- launch ----------------
extern "C" void kernel_launch(void* const* d_in, const int* in_sizes, int n_in,
                              void* d_out, int out_size) {
    const float* x   = (const float*)d_in[0];
    const float* adj = (const float*)d_in[1];
    const float* W0  = (const float*)d_in[2];
    const float* al0 = (const float*)d_in[3];
    const float* ar0 = (const float*)d_in[4];
    const float* b0  = (const float*)d_in[5];
    const float* W1  = (const float*)d_in[6];
    const float* al1 = (const float*)d_in[7];
    const float* ar1 = (const float*)d_in[8];
    const float* b1  = (const float*)d_in[9];
    const float* W2  = (const float*)d_in[10];
    const float* al2 = (const float*)d_in[11];
    const float* ar2 = (const float*)d_in[12];
    const float* b2  = (const float*)d_in[13];
    float* out = (float*)d_out;

    float *feat, *hbuf, *el, *er, *out2;
    cudaGetSymbolAddress((void**)&feat, g_feat);
    cudaGetSymbolAddress((void**)&hbuf, g_h);
    cudaGetSymbolAddress((void**)&el,   g_el);
    cudaGetSymbolAddress((void**)&er,   g_er);
    cudaGetSymbolAddress((void**)&out2, g_out2);

    dim3 t256(256);

    // ---- layer 0 (input: x[:,0], shared across channels) ----
    gemm128<<<dim3(HD / 128, NN / 128, BC), t256>>>(x, W0, feat, FIN, HD,
                                                    (size_t)C * NN * FIN, 0);
    elr_kernel<<<BC * NN, 128>>>(feat, al0, ar0, el, er, DHID);
    agg_kernel<DHID, true><<<dim3(NN / 128, H, BC), t256>>>(adj, feat, el, er, b0, hbuf);

    // ---- layer 1 ----
    gemm128<<<dim3(HD / 128, NN / 128, BC), t256>>>(hbuf, W1, feat, HD, HD,
                                                    (size_t)C * NN * HD, (size_t)NN * HD);
    elr_kernel<<<BC * NN, 128>>>(feat, al1, ar1, el, er, DHID);
    agg_kernel<DHID, true><<<dim3(NN / 128, H, BC), t256>>>(adj, feat, el, er, b1, hbuf);

    // ---- layer 2 ----
    gemm128<<<dim3(HD2 / 128, NN / 128, BC), t256>>>(hbuf, W2, feat, HD, HD2,
                                                     (size_t)C * NN * HD, (size_t)NN * HD);
    elr_kernel<<<BC * NN, 128>>>(feat, al2, ar2, el, er, DOUT);
    agg_kernel<DOUT, false><<<dim3(NN / 128, H, BC), t256>>>(adj, feat, el, er, b2, out2);

    // ---- head mean + concat ----
    mean_kernel<<<(B * NN * C * DOUT + 255) / 256, t256>>>(out2, out);
}